// round 9
// baseline (speedup 1.0000x reference)
#include <cuda_runtime.h>

typedef unsigned long long u64;

// ---------------- DOPRI5 coefficients ----------------
__constant__ float cA[15] = {
    (float)(1.0/5.0),
    (float)(3.0/40.0), (float)(9.0/40.0),
    (float)(44.0/45.0), (float)(-56.0/15.0), (float)(32.0/9.0),
    (float)(19372.0/6561.0), (float)(-25360.0/2187.0), (float)(64448.0/6561.0), (float)(-212.0/729.0),
    (float)(9017.0/3168.0), (float)(-355.0/33.0), (float)(46732.0/5247.0), (float)(49.0/176.0), (float)(-5103.0/18656.0)
};
__constant__ float cB[6] = {
    (float)(35.0/384.0), 0.0f, (float)(500.0/1113.0),
    (float)(125.0/192.0), (float)(-2187.0/6784.0), (float)(11.0/84.0)
};
__constant__ float cC[6] = { 0.0f, (float)(1.0/5.0), (float)(3.0/10.0),
                             (float)(4.0/5.0), (float)(8.0/9.0), 1.0f };

// ---------------- f32x2 helpers ----------------
__device__ __forceinline__ u64 pk2(float lo, float hi) {
    u64 r; asm("mov.b64 %0, {%1, %2};" : "=l"(r) : "f"(lo), "f"(hi)); return r;
}
__device__ __forceinline__ void upk2(u64 v, float& lo, float& hi) {
    asm("mov.b64 {%0, %1}, %2;" : "=f"(lo), "=f"(hi) : "l"(v));
}
__device__ __forceinline__ u64 fma2_(u64 a, u64 b, u64 c) {
    u64 d; asm("fma.rn.f32x2 %0, %1, %2, %3;" : "=l"(d) : "l"(a), "l"(b), "l"(c)); return d;
}
__device__ __forceinline__ u64 mul2_(u64 a, u64 b) {
    u64 d; asm("mul.rn.f32x2 %0, %1, %2;" : "=l"(d) : "l"(a), "l"(b)); return d;
}
__device__ __forceinline__ u64 add2_(u64 a, u64 b) {
    u64 d; asm("add.rn.f32x2 %0, %1, %2;" : "=l"(d) : "l"(a), "l"(b)); return d;
}
__device__ __forceinline__ float tanhap_(float x) {
    float y; asm("tanh.approx.f32 %0, %1;" : "=f"(y) : "f"(x)); return y;
}
__device__ __forceinline__ u64 tanh2a_(u64 g) {
    float l, h; upk2(g, l, h);
    return pk2(tanhap_(l), tanhap_(h));
}
__device__ __forceinline__ float2 f2fma(float a, float2 b, float2 c) {
    return make_float2(fmaf(a, b.x, c.x), fmaf(a, b.y, c.y));
}

// MUFU-free tanh pair: Pade[7/6] convergent of tanh, clamp |x|<=5.5,
// division by bits-trick reciprocal + 3 Newton iterations (all FMA/ALU pipe).
// max abs err ~2e-4 (at clamp edge); <1e-5 for |x|<3.
__device__ __forceinline__ u64 tanh2p_(u64 g) {
    float l, h; upk2(g, l, h);
    l = fminf(fmaxf(l, -5.5f), 5.5f);
    h = fminf(fmaxf(h, -5.5f), 5.5f);
    u64 x = pk2(l, h);
    u64 u = mul2_(x, x);
    const u64 c135135 = pk2(135135.0f, 135135.0f);
    // numerator: a = x*(135135 + u*(17325 + u*(378 + u)))
    u64 t = add2_(u, pk2(378.0f, 378.0f));
    t = fma2_(u, t, pk2(17325.0f, 17325.0f));
    t = fma2_(u, t, c135135);
    u64 a = mul2_(x, t);
    // denominator: s = 135135 + u*(62370 + u*(3150 + 28u))  (always >= 135135 > 0)
    u64 s = fma2_(pk2(28.0f, 28.0f), u, pk2(3150.0f, 3150.0f));
    s = fma2_(u, s, pk2(62370.0f, 62370.0f));
    s = fma2_(u, s, c135135);
    // r = 1/s : bits-trick initial guess (~<10% err) + 3 Newton (err -> ~1e-8)
    float sl, sh; upk2(s, sl, sh);
    unsigned il = 0x7EF311C3u - __float_as_uint(sl);
    unsigned ih = 0x7EF311C3u - __float_as_uint(sh);
    u64 r = pk2(__uint_as_float(il), __uint_as_float(ih));
    u64 ns = s ^ 0x8000000080000000ULL;   // -s (packed sign flip)
    const u64 two2 = pk2(2.0f, 2.0f);
    u64 e;
    e = fma2_(ns, r, two2); r = mul2_(r, e);
    e = fma2_(ns, r, two2); r = mul2_(r, e);
    e = fma2_(ns, r, two2); r = mul2_(r, e);
    return mul2_(a, r);
}

// ---------------- dynamics for FOUR particles (two f32x2 pairs A and B) ----------------
// net1 -> Pade on FMA pipe (MUFU-free); net2/net3 -> tanh.approx (MUFU).
// sw[j][0..15] = duplicated-f32x2 weights:
//   0:W1[j,0] 1:W1[j,1] 2:wb1 3:bb1 4:Wo1  5:W2[j,0] 6:W2[j,1] 7:wb2 8:bb2 9:Wo2
//   10:W3[j,0] 11:W3[j,1] 12:W3[j,2] 13:wb3 14:bb3 15:Wo3
__device__ __forceinline__ void dyn4(float t,
                                     float2 A0, float2 A1, float2 A2,
                                     float2 B0, float2 B1, float2 B2,
                                     float2* kA, float2* kB,
                                     const u64 (*sw)[16]) {
    u64 xa0 = pk2(A0.x, A0.y), xa1 = pk2(A1.x, A1.y), xa2 = pk2(A2.x, A2.y);
    u64 xb0 = pk2(B0.x, B0.y), xb1 = pk2(B1.x, B1.y), xb2 = pk2(B2.x, B2.y);
    u64 tt = pk2(t, t);
    u64 aA1 = 0ULL, aA2 = 0ULL, aA3 = 0ULL;
    u64 aB1 = 0ULL, aB2 = 0ULL, aB3 = 0ULL;

    #pragma unroll 2
    for (int j = 0; j < 64; j++) {
        const ulonglong2* p = reinterpret_cast<const ulonglong2*>(sw[j]);
        ulonglong2 q0 = p[0], q1 = p[1], q2 = p[2], q3 = p[3];
        ulonglong2 q4 = p[4], q5 = p[5], q6 = p[6], q7 = p[7];

        // ---- net 1 (offloaded to FMA-pipe Pade tanh) ----
        u64 b1 = fma2_(q1.x, tt, q1.y);                 // wb1*t + bb1
        u64 gA1 = fma2_(q0.x, xa0, b1); gA1 = fma2_(q0.y, xa1, gA1);
        u64 gB1 = fma2_(q0.x, xb0, b1); gB1 = fma2_(q0.y, xb1, gB1);
        aA1 = fma2_(q2.x, tanh2p_(gA1), aA1);
        aB1 = fma2_(q2.x, tanh2p_(gB1), aB1);

        // ---- net 2 (MUFU tanh) ----
        u64 b2 = fma2_(q3.y, tt, q4.x);                 // wb2*t + bb2
        u64 gA2 = fma2_(q2.y, xa0, b2); gA2 = fma2_(q3.x, xa1, gA2);
        u64 gB2 = fma2_(q2.y, xb0, b2); gB2 = fma2_(q3.x, xb1, gB2);
        aA2 = fma2_(q4.y, tanh2a_(gA2), aA2);
        aB2 = fma2_(q4.y, tanh2a_(gB2), aB2);

        // ---- net 3 (MUFU tanh, 3 state inputs) ----
        u64 b3 = fma2_(q6.y, tt, q7.x);                 // wb3*t + bb3
        u64 gA3 = fma2_(q5.x, xa0, b3); gA3 = fma2_(q5.y, xa1, gA3); gA3 = fma2_(q6.x, xa2, gA3);
        u64 gB3 = fma2_(q5.x, xb0, b3); gB3 = fma2_(q5.y, xb1, gB3); gB3 = fma2_(q6.x, xb2, gB3);
        aA3 = fma2_(q7.y, tanh2a_(gA3), aA3);
        aB3 = fma2_(q7.y, tanh2a_(gB3), aB3);
    }
    float lo, hi;
    upk2(aA1, lo, hi); kA[0] = make_float2(lo, hi);
    upk2(aA2, lo, hi); kA[1] = make_float2(lo, hi);
    upk2(aA3, lo, hi); kA[2] = make_float2(lo, hi);
    upk2(aB1, lo, hi); kB[0] = make_float2(lo, hi);
    upk2(aB2, lo, hi); kB[1] = make_float2(lo, hi);
    upk2(aB3, lo, hi); kB[2] = make_float2(lo, hi);
}

// ---------------- main kernel: 4 particles/thread, phase split ----------------
extern "C" __global__ void __launch_bounds__(128, 4)
ode_kernel(const float* __restrict__ u,
           const float* __restrict__ W1, const float* __restrict__ W2, const float* __restrict__ W3,
           const float* __restrict__ wb1, const float* __restrict__ bb1,
           const float* __restrict__ wb2, const float* __restrict__ bb2,
           const float* __restrict__ wb3, const float* __restrict__ bb3,
           const float* __restrict__ Wo1, const float* __restrict__ Wo2, const float* __restrict__ Wo3,
           float* __restrict__ out, int B)
{
    __shared__ __align__(16) u64 sw[64][16];
    int tid = threadIdx.x;
    for (int idx = tid; idx < 64 * 16; idx += blockDim.x) {
        int j = idx >> 4, f = idx & 15;
        float v;
        switch (f) {
            case 0:  v = W1[2*j];    break;
            case 1:  v = W1[2*j+1];  break;
            case 2:  v = wb1[j];     break;
            case 3:  v = bb1[j];     break;
            case 4:  v = Wo1[j];     break;
            case 5:  v = W2[2*j];    break;
            case 6:  v = W2[2*j+1];  break;
            case 7:  v = wb2[j];     break;
            case 8:  v = bb2[j];     break;
            case 9:  v = Wo2[j];     break;
            case 10: v = W3[3*j];    break;
            case 11: v = W3[3*j+1];  break;
            case 12: v = W3[3*j+2];  break;
            case 13: v = wb3[j];     break;
            case 14: v = bb3[j];     break;
            default: v = Wo3[j];     break;
        }
        sw[j][f] = pk2(v, v);
    }
    __syncthreads();

    const int nquads = B >> 2;
    // even blocks: phase 0 (features); odd blocks: phase 1 (trajectory)
    int phase = blockIdx.x & 1;
    int qid = (blockIdx.x >> 1) * blockDim.x + tid;
    if (qid >= nquads) return;

    const float* up = u + 12 * qid;
    float uv[12];
    #pragma unroll
    for (int i = 0; i < 12; i++) uv[i] = up[i];

    // pair A = particles (4q, 4q+1), pair B = (4q+2, 4q+3)
    float2 xA0 = make_float2(uv[0], uv[3]);
    float2 xA1 = make_float2(uv[1], uv[4]);
    float2 xA2 = make_float2(uv[2], uv[5]);
    float2 xB0 = make_float2(uv[6], uv[9]);
    float2 xB1 = make_float2(uv[7], uv[10]);
    float2 xB2 = make_float2(uv[8], uv[11]);
    const float h   = phase ? (float)(10.0/27.0) : (float)(10.0/24.0);
    const int nseg  = phase ? 9 : 1;
    const int nsub  = phase ? 3 : 24;

    #pragma unroll 1
    for (int sg = 0; sg < nseg; sg++) {
        float t = phase ? (float)sg * (float)(10.0/9.0) : 0.0f;

        #pragma unroll 1
        for (int it = 0; it < nsub; it++) {
            float2 kA[6][3], kB[6][3];   // dynamic-indexed -> local (cheap vs compute)
            #pragma unroll 1
            for (int s = 0; s < 6; s++) {
                float2 aA0 = make_float2(0.f,0.f), aA1 = make_float2(0.f,0.f), aA2 = make_float2(0.f,0.f);
                float2 aB0 = make_float2(0.f,0.f), aB1 = make_float2(0.f,0.f), aB2 = make_float2(0.f,0.f);
                int base = (s * (s - 1)) >> 1;
                for (int m = 0; m < s; m++) {
                    float a = cA[base + m];
                    aA0 = f2fma(a, kA[m][0], aA0);
                    aA1 = f2fma(a, kA[m][1], aA1);
                    aA2 = f2fma(a, kA[m][2], aA2);
                    aB0 = f2fma(a, kB[m][0], aB0);
                    aB1 = f2fma(a, kB[m][1], aB1);
                    aB2 = f2fma(a, kB[m][2], aB2);
                }
                float2 sA0 = f2fma(h, aA0, xA0), sA1 = f2fma(h, aA1, xA1), sA2 = f2fma(h, aA2, xA2);
                float2 sB0 = f2fma(h, aB0, xB0), sB1 = f2fma(h, aB1, xB1), sB2 = f2fma(h, aB2, xB2);
                float ts = fmaf(cC[s], h, t);
                dyn4(ts, sA0, sA1, sA2, sB0, sB1, sB2, kA[s], kB[s], sw);
            }
            float2 aA0 = make_float2(0.f,0.f), aA1 = make_float2(0.f,0.f), aA2 = make_float2(0.f,0.f);
            float2 aB0 = make_float2(0.f,0.f), aB1 = make_float2(0.f,0.f), aB2 = make_float2(0.f,0.f);
            for (int m = 0; m < 6; m++) {
                float b = cB[m];
                aA0 = f2fma(b, kA[m][0], aA0);
                aA1 = f2fma(b, kA[m][1], aA1);
                aA2 = f2fma(b, kA[m][2], aA2);
                aB0 = f2fma(b, kB[m][0], aB0);
                aB1 = f2fma(b, kB[m][1], aB1);
                aB2 = f2fma(b, kB[m][2], aB2);
            }
            xA0 = f2fma(h, aA0, xA0); xA1 = f2fma(h, aA1, xA1); xA2 = f2fma(h, aA2, xA2);
            xB0 = f2fma(h, aB0, xB0); xB1 = f2fma(h, aB1, xB1); xB2 = f2fma(h, aB2, xB2);
            t += h;
        }

        if (phase) {
            float* ot = out + (size_t)3 * B + (size_t)sg * 3 * B + 12 * qid;
            ot[0] = xA0.x; ot[1]  = xA1.x; ot[2]  = xA2.x;
            ot[3] = xA0.y; ot[4]  = xA1.y; ot[5]  = xA2.y;
            ot[6] = xB0.x; ot[7]  = xB1.x; ot[8]  = xB2.x;
            ot[9] = xB0.y; ot[10] = xB1.y; ot[11] = xB2.y;
        }
    }
    if (!phase) {
        float* of = out + 12 * qid;
        of[0] = xA0.x; of[1]  = xA1.x; of[2]  = xA2.x;
        of[3] = xA0.y; of[4]  = xA1.y; of[5]  = xA2.y;
        of[6] = xB0.x; of[7]  = xB1.x; of[8]  = xB2.x;
        of[9] = xB0.y; of[10] = xB1.y; of[11] = xB2.y;
    }
}

extern "C" void kernel_launch(void* const* d_in, const int* in_sizes, int n_in,
                              void* d_out, int out_size) {
    const float* u   = (const float*)d_in[0];
    const float* W1  = (const float*)d_in[1];
    const float* W2  = (const float*)d_in[2];
    const float* W3  = (const float*)d_in[3];
    const float* wb1 = (const float*)d_in[4];
    const float* bb1 = (const float*)d_in[5];
    const float* wb2 = (const float*)d_in[6];
    const float* bb2 = (const float*)d_in[7];
    const float* wb3 = (const float*)d_in[8];
    const float* bb3 = (const float*)d_in[9];
    const float* Wo1 = (const float*)d_in[10];
    const float* Wo2 = (const float*)d_in[11];
    const float* Wo3 = (const float*)d_in[12];
    float* out = (float*)d_out;
    int B = in_sizes[0] / 3;

    int nquads = B >> 2;                    // 32768
    int qblocks = (nquads + 127) / 128;     // 256
    ode_kernel<<<2 * qblocks, 128>>>(u, W1, W2, W3, wb1, bb1, wb2, bb2, wb3, bb3,
                                     Wo1, Wo2, Wo3, out, B);
}

// round 10
// speedup vs baseline: 1.2669x; 1.2669x over previous
#include <cuda_runtime.h>

typedef unsigned long long u64;

// ---------------- DOPRI5 coefficients ----------------
__constant__ float cA[15] = {
    (float)(1.0/5.0),
    (float)(3.0/40.0), (float)(9.0/40.0),
    (float)(44.0/45.0), (float)(-56.0/15.0), (float)(32.0/9.0),
    (float)(19372.0/6561.0), (float)(-25360.0/2187.0), (float)(64448.0/6561.0), (float)(-212.0/729.0),
    (float)(9017.0/3168.0), (float)(-355.0/33.0), (float)(46732.0/5247.0), (float)(49.0/176.0), (float)(-5103.0/18656.0)
};
__constant__ float cB[6] = {
    (float)(35.0/384.0), 0.0f, (float)(500.0/1113.0),
    (float)(125.0/192.0), (float)(-2187.0/6784.0), (float)(11.0/84.0)
};
__constant__ float cC[6] = { 0.0f, (float)(1.0/5.0), (float)(3.0/10.0),
                             (float)(4.0/5.0), (float)(8.0/9.0), 1.0f };

// ---------------- f32x2 helpers ----------------
__device__ __forceinline__ u64 pk2(float lo, float hi) {
    u64 r; asm("mov.b64 %0, {%1, %2};" : "=l"(r) : "f"(lo), "f"(hi)); return r;
}
__device__ __forceinline__ void upk2(u64 v, float& lo, float& hi) {
    asm("mov.b64 {%0, %1}, %2;" : "=f"(lo), "=f"(hi) : "l"(v));
}
__device__ __forceinline__ u64 fma2_(u64 a, u64 b, u64 c) {
    u64 d; asm("fma.rn.f32x2 %0, %1, %2, %3;" : "=l"(d) : "l"(a), "l"(b), "l"(c)); return d;
}
__device__ __forceinline__ float2 f2fma(float a, float2 b, float2 c) {
    return make_float2(fmaf(a, b.x, c.x), fmaf(a, b.y, c.y));
}

// two tanhs in ONE MUFU op via tanh.approx.f16x2; fp32 gate in, fp32 accumulate out.
// (Same numerics as R7, which measured rel_err = 5.78e-4 end-to-end.)
__device__ __forceinline__ u64 tanh2h_(u64 g) {
    float lo, hi; upk2(g, lo, hi);
    unsigned int hp, ht;
    asm("cvt.rn.f16x2.f32 %0, %1, %2;" : "=r"(hp) : "f"(hi), "f"(lo));
    asm("tanh.approx.f16x2 %0, %1;" : "=r"(ht) : "r"(hp));
    float rlo, rhi;
    asm("{ .reg .b16 l, h;\n\t"
        "  mov.b32 {l, h}, %2;\n\t"
        "  cvt.f32.f16 %0, l;\n\t"
        "  cvt.f32.f16 %1, h; }"
        : "=f"(rlo), "=f"(rhi) : "r"(ht));
    return pk2(rlo, rhi);
}

// ---------------- dynamics for EIGHT particles (four f32x2 pairs) ----------------
// sw[j][0..15] = duplicated-f32x2 weights:
//   0:W1[j,0] 1:W1[j,1] 2:wb1 3:bb1 4:Wo1  5:W2[j,0] 6:W2[j,1] 7:wb2 8:bb2 9:Wo2
//   10:W3[j,0] 11:W3[j,1] 12:W3[j,2] 13:wb3 14:bb3 15:Wo3
// Weights loaded ONCE per j and used by all 4 pairs; biases computed once per j.
__device__ __forceinline__ void dyn8(float t, const u64 x[4][3], float2 k[4][3],
                                     const u64 (*sw)[16]) {
    u64 tt = pk2(t, t);
    u64 acc[4][3];
    #pragma unroll
    for (int p = 0; p < 4; p++)
        #pragma unroll
        for (int n = 0; n < 3; n++) acc[p][n] = 0ULL;

    #pragma unroll 2
    for (int j = 0; j < 64; j++) {
        const ulonglong2* pw = reinterpret_cast<const ulonglong2*>(sw[j]);
        ulonglong2 q0 = pw[0], q1 = pw[1], q2 = pw[2], q3 = pw[3];
        ulonglong2 q4 = pw[4], q5 = pw[5], q6 = pw[6], q7 = pw[7];

        u64 b1 = fma2_(q1.x, tt, q1.y);   // wb1*t + bb1
        u64 b2 = fma2_(q3.y, tt, q4.x);   // wb2*t + bb2
        u64 b3 = fma2_(q6.y, tt, q7.x);   // wb3*t + bb3

        #pragma unroll
        for (int p = 0; p < 4; p++) {
            u64 g1 = fma2_(q0.x, x[p][0], b1);
            g1 = fma2_(q0.y, x[p][1], g1);
            acc[p][0] = fma2_(q2.x, tanh2h_(g1), acc[p][0]);

            u64 g2 = fma2_(q2.y, x[p][0], b2);
            g2 = fma2_(q3.x, x[p][1], g2);
            acc[p][1] = fma2_(q4.y, tanh2h_(g2), acc[p][1]);

            u64 g3 = fma2_(q5.x, x[p][0], b3);
            g3 = fma2_(q5.y, x[p][1], g3);
            g3 = fma2_(q6.x, x[p][2], g3);
            acc[p][2] = fma2_(q7.y, tanh2h_(g3), acc[p][2]);
        }
    }
    #pragma unroll
    for (int p = 0; p < 4; p++)
        #pragma unroll
        for (int n = 0; n < 3; n++) {
            float lo, hi; upk2(acc[p][n], lo, hi);
            k[p][n] = make_float2(lo, hi);
        }
}

// ---------------- main kernel: 8 particles/thread, phase split across blocks ----------------
extern "C" __global__ void __launch_bounds__(64, 4)
ode_kernel(const float* __restrict__ u,
           const float* __restrict__ W1, const float* __restrict__ W2, const float* __restrict__ W3,
           const float* __restrict__ wb1, const float* __restrict__ bb1,
           const float* __restrict__ wb2, const float* __restrict__ bb2,
           const float* __restrict__ wb3, const float* __restrict__ bb3,
           const float* __restrict__ Wo1, const float* __restrict__ Wo2, const float* __restrict__ Wo3,
           float* __restrict__ out, int B)
{
    __shared__ __align__(16) u64 sw[64][16];
    int tid = threadIdx.x;
    for (int idx = tid; idx < 64 * 16; idx += blockDim.x) {
        int j = idx >> 4, f = idx & 15;
        float v;
        switch (f) {
            case 0:  v = W1[2*j];    break;
            case 1:  v = W1[2*j+1];  break;
            case 2:  v = wb1[j];     break;
            case 3:  v = bb1[j];     break;
            case 4:  v = Wo1[j];     break;
            case 5:  v = W2[2*j];    break;
            case 6:  v = W2[2*j+1];  break;
            case 7:  v = wb2[j];     break;
            case 8:  v = bb2[j];     break;
            case 9:  v = Wo2[j];     break;
            case 10: v = W3[3*j];    break;
            case 11: v = W3[3*j+1];  break;
            case 12: v = W3[3*j+2];  break;
            case 13: v = wb3[j];     break;
            case 14: v = bb3[j];     break;
            default: v = Wo3[j];     break;
        }
        sw[j][f] = pk2(v, v);
    }
    __syncthreads();

    const int nocts = B >> 3;
    // even blocks: phase 0 (features); odd blocks: phase 1 (trajectory)
    int phase = blockIdx.x & 1;
    int oid = (blockIdx.x >> 1) * blockDim.x + tid;
    if (oid >= nocts) return;

    const float* up = u + 24 * oid;
    float uv[24];
    #pragma unroll
    for (int i = 0; i < 24; i++) uv[i] = up[i];

    // pair p holds particles (8o + 2p, 8o + 2p + 1) in (lo, hi) lanes
    float2 xs[4][3];
    #pragma unroll
    for (int p = 0; p < 4; p++)
        #pragma unroll
        for (int c = 0; c < 3; c++)
            xs[p][c] = make_float2(uv[6*p + c], uv[6*p + 3 + c]);

    const float h   = phase ? (float)(10.0/27.0) : (float)(10.0/24.0);
    const int nseg  = phase ? 9 : 1;
    const int nsub  = phase ? 3 : 24;

    #pragma unroll 1
    for (int sg = 0; sg < nseg; sg++) {
        float t = phase ? (float)sg * (float)(10.0/9.0) : 0.0f;

        #pragma unroll 1
        for (int it = 0; it < nsub; it++) {
            float2 k[6][4][3];   // dynamic s-index -> local (cheap vs compute)
            #pragma unroll 1
            for (int s = 0; s < 6; s++) {
                float2 a[4][3];
                #pragma unroll
                for (int p = 0; p < 4; p++)
                    #pragma unroll
                    for (int c = 0; c < 3; c++) a[p][c] = make_float2(0.f, 0.f);
                int base = (s * (s - 1)) >> 1;
                for (int m = 0; m < s; m++) {
                    float ac = cA[base + m];
                    #pragma unroll
                    for (int p = 0; p < 4; p++)
                        #pragma unroll
                        for (int c = 0; c < 3; c++)
                            a[p][c] = f2fma(ac, k[m][p][c], a[p][c]);
                }
                u64 xst[4][3];
                #pragma unroll
                for (int p = 0; p < 4; p++)
                    #pragma unroll
                    for (int c = 0; c < 3; c++) {
                        float2 sv = f2fma(h, a[p][c], xs[p][c]);
                        xst[p][c] = pk2(sv.x, sv.y);
                    }
                float ts = fmaf(cC[s], h, t);
                dyn8(ts, xst, k[s], sw);
            }
            // x += h * (b1 k1 + b3 k3 + b4 k4 + b5 k5 + b6 k6)
            float2 a[4][3];
            #pragma unroll
            for (int p = 0; p < 4; p++)
                #pragma unroll
                for (int c = 0; c < 3; c++) a[p][c] = make_float2(0.f, 0.f);
            for (int m = 0; m < 6; m++) {
                float bc = cB[m];
                #pragma unroll
                for (int p = 0; p < 4; p++)
                    #pragma unroll
                    for (int c = 0; c < 3; c++)
                        a[p][c] = f2fma(bc, k[m][p][c], a[p][c]);
            }
            #pragma unroll
            for (int p = 0; p < 4; p++)
                #pragma unroll
                for (int c = 0; c < 3; c++)
                    xs[p][c] = f2fma(h, a[p][c], xs[p][c]);
            t += h;
        }

        if (phase) {
            float* ot = out + (size_t)3 * B + (size_t)sg * 3 * B + 24 * oid;
            #pragma unroll
            for (int p = 0; p < 4; p++) {
                ot[6*p + 0] = xs[p][0].x; ot[6*p + 1] = xs[p][1].x; ot[6*p + 2] = xs[p][2].x;
                ot[6*p + 3] = xs[p][0].y; ot[6*p + 4] = xs[p][1].y; ot[6*p + 5] = xs[p][2].y;
            }
        }
    }
    if (!phase) {
        float* of = out + 24 * oid;
        #pragma unroll
        for (int p = 0; p < 4; p++) {
            of[6*p + 0] = xs[p][0].x; of[6*p + 1] = xs[p][1].x; of[6*p + 2] = xs[p][2].x;
            of[6*p + 3] = xs[p][0].y; of[6*p + 4] = xs[p][1].y; of[6*p + 5] = xs[p][2].y;
        }
    }
}

extern "C" void kernel_launch(void* const* d_in, const int* in_sizes, int n_in,
                              void* d_out, int out_size) {
    const float* u   = (const float*)d_in[0];
    const float* W1  = (const float*)d_in[1];
    const float* W2  = (const float*)d_in[2];
    const float* W3  = (const float*)d_in[3];
    const float* wb1 = (const float*)d_in[4];
    const float* bb1 = (const float*)d_in[5];
    const float* wb2 = (const float*)d_in[6];
    const float* bb2 = (const float*)d_in[7];
    const float* wb3 = (const float*)d_in[8];
    const float* bb3 = (const float*)d_in[9];
    const float* Wo1 = (const float*)d_in[10];
    const float* Wo2 = (const float*)d_in[11];
    const float* Wo3 = (const float*)d_in[12];
    float* out = (float*)d_out;
    int B = in_sizes[0] / 3;

    int nocts = B >> 3;                     // 16384
    int oblocks = (nocts + 63) / 64;        // 256
    ode_kernel<<<2 * oblocks, 64>>>(u, W1, W2, W3, wb1, bb1, wb2, bb2, wb3, bb3,
                                    Wo1, Wo2, Wo3, out, B);
}

// round 11
// speedup vs baseline: 1.2956x; 1.0227x over previous
#include <cuda_runtime.h>

typedef unsigned long long u64;

// ---------------- DOPRI5 coefficients ----------------
__constant__ float cA[15] = {
    (float)(1.0/5.0),
    (float)(3.0/40.0), (float)(9.0/40.0),
    (float)(44.0/45.0), (float)(-56.0/15.0), (float)(32.0/9.0),
    (float)(19372.0/6561.0), (float)(-25360.0/2187.0), (float)(64448.0/6561.0), (float)(-212.0/729.0),
    (float)(9017.0/3168.0), (float)(-355.0/33.0), (float)(46732.0/5247.0), (float)(49.0/176.0), (float)(-5103.0/18656.0)
};
__constant__ float cB[6] = {
    (float)(35.0/384.0), 0.0f, (float)(500.0/1113.0),
    (float)(125.0/192.0), (float)(-2187.0/6784.0), (float)(11.0/84.0)
};
__constant__ float cC[6] = { 0.0f, (float)(1.0/5.0), (float)(3.0/10.0),
                             (float)(4.0/5.0), (float)(8.0/9.0), 1.0f };

// ---------------- f32x2 helpers ----------------
__device__ __forceinline__ u64 pk2(float lo, float hi) {
    u64 r; asm("mov.b64 %0, {%1, %2};" : "=l"(r) : "f"(lo), "f"(hi)); return r;
}
__device__ __forceinline__ void upk2(u64 v, float& lo, float& hi) {
    asm("mov.b64 {%0, %1}, %2;" : "=f"(lo), "=f"(hi) : "l"(v));
}
__device__ __forceinline__ u64 fma2_(u64 a, u64 b, u64 c) {
    u64 d; asm("fma.rn.f32x2 %0, %1, %2, %3;" : "=l"(d) : "l"(a), "l"(b), "l"(c)); return d;
}
__device__ __forceinline__ u64 mul2_(u64 a, u64 b) {
    u64 d; asm("mul.rn.f32x2 %0, %1, %2;" : "=l"(d) : "l"(a), "l"(b)); return d;
}
__device__ __forceinline__ u64 add2_(u64 a, u64 b) {
    u64 d; asm("add.rn.f32x2 %0, %1, %2;" : "=l"(d) : "l"(a), "l"(b)); return d;
}
__device__ __forceinline__ float tanhap_(float x) {
    float y; asm("tanh.approx.f32 %0, %1;" : "=f"(y) : "f"(x)); return y;
}
__device__ __forceinline__ u64 tanh2a_(u64 g) {
    float l, h; upk2(g, l, h);
    return pk2(tanhap_(l), tanhap_(h));
}
__device__ __forceinline__ float2 f2fma(float a, float2 b, float2 c) {
    return make_float2(fmaf(a, b.x, c.x), fmaf(a, b.y, c.y));
}

// MUFU-free tanh pair: Pade[7/6], clamp |x|<=5.5, bits-trick rcp + 2 Newton.
// 13 f32x2 FMA-pipe instrs + ~7 ALU-pipe. max abs err ~2e-4 (clamp edge), ~1e-5 typical.
__device__ __forceinline__ u64 tanh2p_(u64 g) {
    float l, h; upk2(g, l, h);
    l = fminf(fmaxf(l, -5.5f), 5.5f);           // FMNMX -> alu pipe
    h = fminf(fmaxf(h, -5.5f), 5.5f);
    u64 x = pk2(l, h);
    u64 u = mul2_(x, x);
    const u64 c135135 = pk2(135135.0f, 135135.0f);
    // numerator a = x*(135135 + u*(17325 + u*(378 + u)))
    u64 t = add2_(u, pk2(378.0f, 378.0f));
    t = fma2_(u, t, pk2(17325.0f, 17325.0f));
    t = fma2_(u, t, c135135);
    u64 a = mul2_(x, t);
    // denominator s = 135135 + u*(62370 + u*(3150 + 28u))   (>= 135135 > 0)
    u64 s = fma2_(pk2(28.0f, 28.0f), u, pk2(3150.0f, 3150.0f));
    s = fma2_(u, s, pk2(62370.0f, 62370.0f));
    s = fma2_(u, s, c135135);
    // r = 1/s : bits-trick guess (alu) + 2 Newton (rel err ~1.3e-5)
    float sl, sh; upk2(s, sl, sh);
    unsigned il = 0x7EF311C3u - __float_as_uint(sl);
    unsigned ih = 0x7EF311C3u - __float_as_uint(sh);
    u64 r = pk2(__uint_as_float(il), __uint_as_float(ih));
    u64 ns = s ^ 0x8000000080000000ULL;         // -s (packed sign flip, alu)
    const u64 two2 = pk2(2.0f, 2.0f);
    u64 e;
    e = fma2_(ns, r, two2); r = mul2_(r, e);
    e = fma2_(ns, r, two2); r = mul2_(r, e);
    return mul2_(a, r);
}

// ---------------- dynamics for FOUR particles (two f32x2 pairs A and B) ----------------
// f = 1/6 MUFU offload: net1-pairA uses the FMA-pipe Pade; the other 5 pair-tanhs use MUFU.
// sw[j][0..15] = duplicated-f32x2 weights:
//   0:W1[j,0] 1:W1[j,1] 2:wb1 3:bb1 4:Wo1  5:W2[j,0] 6:W2[j,1] 7:wb2 8:bb2 9:Wo2
//   10:W3[j,0] 11:W3[j,1] 12:W3[j,2] 13:wb3 14:bb3 15:Wo3
__device__ __forceinline__ void dyn4(float t,
                                     float2 A0, float2 A1, float2 A2,
                                     float2 B0, float2 B1, float2 B2,
                                     float2* kA, float2* kB,
                                     const u64 (*sw)[16]) {
    u64 xa0 = pk2(A0.x, A0.y), xa1 = pk2(A1.x, A1.y), xa2 = pk2(A2.x, A2.y);
    u64 xb0 = pk2(B0.x, B0.y), xb1 = pk2(B1.x, B1.y), xb2 = pk2(B2.x, B2.y);
    u64 tt = pk2(t, t);
    u64 aA1 = 0ULL, aA2 = 0ULL, aA3 = 0ULL;
    u64 aB1 = 0ULL, aB2 = 0ULL, aB3 = 0ULL;

    #pragma unroll 2
    for (int j = 0; j < 64; j++) {
        const ulonglong2* p = reinterpret_cast<const ulonglong2*>(sw[j]);
        ulonglong2 q0 = p[0], q1 = p[1], q2 = p[2], q3 = p[3];
        ulonglong2 q4 = p[4], q5 = p[5], q6 = p[6], q7 = p[7];

        // ---- net 1 ----
        u64 b1 = fma2_(q1.x, tt, q1.y);                 // wb1*t + bb1
        u64 gA1 = fma2_(q0.x, xa0, b1); gA1 = fma2_(q0.y, xa1, gA1);
        u64 gB1 = fma2_(q0.x, xb0, b1); gB1 = fma2_(q0.y, xb1, gB1);
        aA1 = fma2_(q2.x, tanh2p_(gA1), aA1);           // FMA-pipe Pade (offloaded)
        aB1 = fma2_(q2.x, tanh2a_(gB1), aB1);           // MUFU

        // ---- net 2 (MUFU) ----
        u64 b2 = fma2_(q3.y, tt, q4.x);                 // wb2*t + bb2
        u64 gA2 = fma2_(q2.y, xa0, b2); gA2 = fma2_(q3.x, xa1, gA2);
        u64 gB2 = fma2_(q2.y, xb0, b2); gB2 = fma2_(q3.x, xb1, gB2);
        aA2 = fma2_(q4.y, tanh2a_(gA2), aA2);
        aB2 = fma2_(q4.y, tanh2a_(gB2), aB2);

        // ---- net 3 (MUFU, 3 state inputs) ----
        u64 b3 = fma2_(q6.y, tt, q7.x);                 // wb3*t + bb3
        u64 gA3 = fma2_(q5.x, xa0, b3); gA3 = fma2_(q5.y, xa1, gA3); gA3 = fma2_(q6.x, xa2, gA3);
        u64 gB3 = fma2_(q5.x, xb0, b3); gB3 = fma2_(q5.y, xb1, gB3); gB3 = fma2_(q6.x, xb2, gB3);
        aA3 = fma2_(q7.y, tanh2a_(gA3), aA3);
        aB3 = fma2_(q7.y, tanh2a_(gB3), aB3);
    }
    float lo, hi;
    upk2(aA1, lo, hi); kA[0] = make_float2(lo, hi);
    upk2(aA2, lo, hi); kA[1] = make_float2(lo, hi);
    upk2(aA3, lo, hi); kA[2] = make_float2(lo, hi);
    upk2(aB1, lo, hi); kB[0] = make_float2(lo, hi);
    upk2(aB2, lo, hi); kB[1] = make_float2(lo, hi);
    upk2(aB3, lo, hi); kB[2] = make_float2(lo, hi);
}

// ---------------- main kernel: 4 particles/thread, phase split ----------------
extern "C" __global__ void __launch_bounds__(128, 4)
ode_kernel(const float* __restrict__ u,
           const float* __restrict__ W1, const float* __restrict__ W2, const float* __restrict__ W3,
           const float* __restrict__ wb1, const float* __restrict__ bb1,
           const float* __restrict__ wb2, const float* __restrict__ bb2,
           const float* __restrict__ wb3, const float* __restrict__ bb3,
           const float* __restrict__ Wo1, const float* __restrict__ Wo2, const float* __restrict__ Wo3,
           float* __restrict__ out, int B)
{
    __shared__ __align__(16) u64 sw[64][16];
    int tid = threadIdx.x;
    for (int idx = tid; idx < 64 * 16; idx += blockDim.x) {
        int j = idx >> 4, f = idx & 15;
        float v;
        switch (f) {
            case 0:  v = W1[2*j];    break;
            case 1:  v = W1[2*j+1];  break;
            case 2:  v = wb1[j];     break;
            case 3:  v = bb1[j];     break;
            case 4:  v = Wo1[j];     break;
            case 5:  v = W2[2*j];    break;
            case 6:  v = W2[2*j+1];  break;
            case 7:  v = wb2[j];     break;
            case 8:  v = bb2[j];     break;
            case 9:  v = Wo2[j];     break;
            case 10: v = W3[3*j];    break;
            case 11: v = W3[3*j+1];  break;
            case 12: v = W3[3*j+2];  break;
            case 13: v = wb3[j];     break;
            case 14: v = bb3[j];     break;
            default: v = Wo3[j];     break;
        }
        sw[j][f] = pk2(v, v);
    }
    __syncthreads();

    const int nquads = B >> 2;
    // even blocks: phase 0 (features); odd blocks: phase 1 (trajectory)
    int phase = blockIdx.x & 1;
    int qid = (blockIdx.x >> 1) * blockDim.x + tid;
    if (qid >= nquads) return;

    const float* up = u + 12 * qid;
    float uv[12];
    #pragma unroll
    for (int i = 0; i < 12; i++) uv[i] = up[i];

    // pair A = particles (4q, 4q+1), pair B = (4q+2, 4q+3)
    float2 xA0 = make_float2(uv[0], uv[3]);
    float2 xA1 = make_float2(uv[1], uv[4]);
    float2 xA2 = make_float2(uv[2], uv[5]);
    float2 xB0 = make_float2(uv[6], uv[9]);
    float2 xB1 = make_float2(uv[7], uv[10]);
    float2 xB2 = make_float2(uv[8], uv[11]);
    const float h   = phase ? (float)(10.0/27.0) : (float)(10.0/24.0);
    const int nseg  = phase ? 9 : 1;
    const int nsub  = phase ? 3 : 24;

    #pragma unroll 1
    for (int sg = 0; sg < nseg; sg++) {
        float t = phase ? (float)sg * (float)(10.0/9.0) : 0.0f;

        #pragma unroll 1
        for (int it = 0; it < nsub; it++) {
            float2 kA[6][3], kB[6][3];   // dynamic-indexed -> local (cheap vs compute)
            #pragma unroll 1
            for (int s = 0; s < 6; s++) {
                float2 aA0 = make_float2(0.f,0.f), aA1 = make_float2(0.f,0.f), aA2 = make_float2(0.f,0.f);
                float2 aB0 = make_float2(0.f,0.f), aB1 = make_float2(0.f,0.f), aB2 = make_float2(0.f,0.f);
                int base = (s * (s - 1)) >> 1;
                for (int m = 0; m < s; m++) {
                    float a = cA[base + m];
                    aA0 = f2fma(a, kA[m][0], aA0);
                    aA1 = f2fma(a, kA[m][1], aA1);
                    aA2 = f2fma(a, kA[m][2], aA2);
                    aB0 = f2fma(a, kB[m][0], aB0);
                    aB1 = f2fma(a, kB[m][1], aB1);
                    aB2 = f2fma(a, kB[m][2], aB2);
                }
                float2 sA0 = f2fma(h, aA0, xA0), sA1 = f2fma(h, aA1, xA1), sA2 = f2fma(h, aA2, xA2);
                float2 sB0 = f2fma(h, aB0, xB0), sB1 = f2fma(h, aB1, xB1), sB2 = f2fma(h, aB2, xB2);
                float ts = fmaf(cC[s], h, t);
                dyn4(ts, sA0, sA1, sA2, sB0, sB1, sB2, kA[s], kB[s], sw);
            }
            float2 aA0 = make_float2(0.f,0.f), aA1 = make_float2(0.f,0.f), aA2 = make_float2(0.f,0.f);
            float2 aB0 = make_float2(0.f,0.f), aB1 = make_float2(0.f,0.f), aB2 = make_float2(0.f,0.f);
            for (int m = 0; m < 6; m++) {
                float b = cB[m];
                aA0 = f2fma(b, kA[m][0], aA0);
                aA1 = f2fma(b, kA[m][1], aA1);
                aA2 = f2fma(b, kA[m][2], aA2);
                aB0 = f2fma(b, kB[m][0], aB0);
                aB1 = f2fma(b, kB[m][1], aB1);
                aB2 = f2fma(b, kB[m][2], aB2);
            }
            xA0 = f2fma(h, aA0, xA0); xA1 = f2fma(h, aA1, xA1); xA2 = f2fma(h, aA2, xA2);
            xB0 = f2fma(h, aB0, xB0); xB1 = f2fma(h, aB1, xB1); xB2 = f2fma(h, aB2, xB2);
            t += h;
        }

        if (phase) {
            float* ot = out + (size_t)3 * B + (size_t)sg * 3 * B + 12 * qid;
            ot[0] = xA0.x; ot[1]  = xA1.x; ot[2]  = xA2.x;
            ot[3] = xA0.y; ot[4]  = xA1.y; ot[5]  = xA2.y;
            ot[6] = xB0.x; ot[7]  = xB1.x; ot[8]  = xB2.x;
            ot[9] = xB0.y; ot[10] = xB1.y; ot[11] = xB2.y;
        }
    }
    if (!phase) {
        float* of = out + 12 * qid;
        of[0] = xA0.x; of[1]  = xA1.x; of[2]  = xA2.x;
        of[3] = xA0.y; of[4]  = xA1.y; of[5]  = xA2.y;
        of[6] = xB0.x; of[7]  = xB1.x; of[8]  = xB2.x;
        of[9] = xB0.y; of[10] = xB1.y; of[11] = xB2.y;
    }
}

extern "C" void kernel_launch(void* const* d_in, const int* in_sizes, int n_in,
                              void* d_out, int out_size) {
    const float* u   = (const float*)d_in[0];
    const float* W1  = (const float*)d_in[1];
    const float* W2  = (const float*)d_in[2];
    const float* W3  = (const float*)d_in[3];
    const float* wb1 = (const float*)d_in[4];
    const float* bb1 = (const float*)d_in[5];
    const float* wb2 = (const float*)d_in[6];
    const float* bb2 = (const float*)d_in[7];
    const float* wb3 = (const float*)d_in[8];
    const float* bb3 = (const float*)d_in[9];
    const float* Wo1 = (const float*)d_in[10];
    const float* Wo2 = (const float*)d_in[11];
    const float* Wo3 = (const float*)d_in[12];
    float* out = (float*)d_out;
    int B = in_sizes[0] / 3;

    int nquads = B >> 2;                    // 32768
    int qblocks = (nquads + 127) / 128;     // 256
    ode_kernel<<<2 * qblocks, 128>>>(u, W1, W2, W3, wb1, bb1, wb2, bb2, wb3, bb3,
                                     Wo1, Wo2, Wo3, out, B);
}

// round 12
// speedup vs baseline: 1.4001x; 1.0807x over previous
#include <cuda_runtime.h>

typedef unsigned long long u64;

// ---------------- DOPRI5 coefficients ----------------
__constant__ float cA[15] = {
    (float)(1.0/5.0),
    (float)(3.0/40.0), (float)(9.0/40.0),
    (float)(44.0/45.0), (float)(-56.0/15.0), (float)(32.0/9.0),
    (float)(19372.0/6561.0), (float)(-25360.0/2187.0), (float)(64448.0/6561.0), (float)(-212.0/729.0),
    (float)(9017.0/3168.0), (float)(-355.0/33.0), (float)(46732.0/5247.0), (float)(49.0/176.0), (float)(-5103.0/18656.0)
};
__constant__ float cB[6] = {
    (float)(35.0/384.0), 0.0f, (float)(500.0/1113.0),
    (float)(125.0/192.0), (float)(-2187.0/6784.0), (float)(11.0/84.0)
};
__constant__ float cC[6] = { 0.0f, (float)(1.0/5.0), (float)(3.0/10.0),
                             (float)(4.0/5.0), (float)(8.0/9.0), 1.0f };

// ---------------- f32x2 helpers ----------------
__device__ __forceinline__ u64 pk2(float lo, float hi) {
    u64 r; asm("mov.b64 %0, {%1, %2};" : "=l"(r) : "f"(lo), "f"(hi)); return r;
}
__device__ __forceinline__ void upk2(u64 v, float& lo, float& hi) {
    asm("mov.b64 {%0, %1}, %2;" : "=f"(lo), "=f"(hi) : "l"(v));
}
__device__ __forceinline__ u64 fma2_(u64 a, u64 b, u64 c) {
    u64 d; asm("fma.rn.f32x2 %0, %1, %2, %3;" : "=l"(d) : "l"(a), "l"(b), "l"(c)); return d;
}
__device__ __forceinline__ float tanhap_(float x) {
    float y; asm("tanh.approx.f32 %0, %1;" : "=f"(y) : "f"(x)); return y;
}
// scalar HW tanh pair (2 MUFU) — the accuracy-proven encoding (rel_err 9e-7 end-to-end)
__device__ __forceinline__ u64 tanh2a_(u64 g) {
    float l, h; upk2(g, l, h);
    return pk2(tanhap_(l), tanhap_(h));
}
__device__ __forceinline__ float2 f2fma(float a, float2 b, float2 c) {
    return make_float2(fmaf(a, b.x, c.x), fmaf(a, b.y, c.y));
}

// ---------------- dynamics for EIGHT particles (four f32x2 pairs) ----------------
// sw[j][0..15] = duplicated-f32x2 weights:
//   0:W1[j,0] 1:W1[j,1] 2:wb1 3:bb1 4:Wo1  5:W2[j,0] 6:W2[j,1] 7:wb2 8:bb2 9:Wo2
//   10:W3[j,0] 11:W3[j,1] 12:W3[j,2] 13:wb3 14:bb3 15:Wo3
// Weights loaded ONCE per j for all 4 pairs (halves LDS/particle vs quad kernel);
// biases computed once per j.
__device__ __forceinline__ void dyn8(float t, const u64 x[4][3], float2 k[4][3],
                                     const u64 (*sw)[16]) {
    u64 tt = pk2(t, t);
    u64 acc[4][3];
    #pragma unroll
    for (int p = 0; p < 4; p++)
        #pragma unroll
        for (int n = 0; n < 3; n++) acc[p][n] = 0ULL;

    #pragma unroll 2
    for (int j = 0; j < 64; j++) {
        const ulonglong2* pw = reinterpret_cast<const ulonglong2*>(sw[j]);
        ulonglong2 q0 = pw[0], q1 = pw[1], q2 = pw[2], q3 = pw[3];
        ulonglong2 q4 = pw[4], q5 = pw[5], q6 = pw[6], q7 = pw[7];

        u64 b1 = fma2_(q1.x, tt, q1.y);   // wb1*t + bb1
        u64 b2 = fma2_(q3.y, tt, q4.x);   // wb2*t + bb2
        u64 b3 = fma2_(q6.y, tt, q7.x);   // wb3*t + bb3

        #pragma unroll
        for (int p = 0; p < 4; p++) {
            u64 g1 = fma2_(q0.x, x[p][0], b1);
            g1 = fma2_(q0.y, x[p][1], g1);
            acc[p][0] = fma2_(q2.x, tanh2a_(g1), acc[p][0]);

            u64 g2 = fma2_(q2.y, x[p][0], b2);
            g2 = fma2_(q3.x, x[p][1], g2);
            acc[p][1] = fma2_(q4.y, tanh2a_(g2), acc[p][1]);

            u64 g3 = fma2_(q5.x, x[p][0], b3);
            g3 = fma2_(q5.y, x[p][1], g3);
            g3 = fma2_(q6.x, x[p][2], g3);
            acc[p][2] = fma2_(q7.y, tanh2a_(g3), acc[p][2]);
        }
    }
    #pragma unroll
    for (int p = 0; p < 4; p++)
        #pragma unroll
        for (int n = 0; n < 3; n++) {
            float lo, hi; upk2(acc[p][n], lo, hi);
            k[p][n] = make_float2(lo, hi);
        }
}

// ---------------- main kernel: 8 particles/thread, phase split across blocks ----------------
extern "C" __global__ void __launch_bounds__(64, 4)
ode_kernel(const float* __restrict__ u,
           const float* __restrict__ W1, const float* __restrict__ W2, const float* __restrict__ W3,
           const float* __restrict__ wb1, const float* __restrict__ bb1,
           const float* __restrict__ wb2, const float* __restrict__ bb2,
           const float* __restrict__ wb3, const float* __restrict__ bb3,
           const float* __restrict__ Wo1, const float* __restrict__ Wo2, const float* __restrict__ Wo3,
           float* __restrict__ out, int B)
{
    __shared__ __align__(16) u64 sw[64][16];
    int tid = threadIdx.x;
    for (int idx = tid; idx < 64 * 16; idx += blockDim.x) {
        int j = idx >> 4, f = idx & 15;
        float v;
        switch (f) {
            case 0:  v = W1[2*j];    break;
            case 1:  v = W1[2*j+1];  break;
            case 2:  v = wb1[j];     break;
            case 3:  v = bb1[j];     break;
            case 4:  v = Wo1[j];     break;
            case 5:  v = W2[2*j];    break;
            case 6:  v = W2[2*j+1];  break;
            case 7:  v = wb2[j];     break;
            case 8:  v = bb2[j];     break;
            case 9:  v = Wo2[j];     break;
            case 10: v = W3[3*j];    break;
            case 11: v = W3[3*j+1];  break;
            case 12: v = W3[3*j+2];  break;
            case 13: v = wb3[j];     break;
            case 14: v = bb3[j];     break;
            default: v = Wo3[j];     break;
        }
        sw[j][f] = pk2(v, v);
    }
    __syncthreads();

    const int nocts = B >> 3;
    // even blocks: phase 0 (features); odd blocks: phase 1 (trajectory)
    int phase = blockIdx.x & 1;
    int oid = (blockIdx.x >> 1) * blockDim.x + tid;
    if (oid >= nocts) return;

    const float* up = u + 24 * oid;
    float uv[24];
    #pragma unroll
    for (int i = 0; i < 24; i++) uv[i] = up[i];

    // pair p holds particles (8o + 2p, 8o + 2p + 1) in (lo, hi) lanes
    float2 xs[4][3];
    #pragma unroll
    for (int p = 0; p < 4; p++)
        #pragma unroll
        for (int c = 0; c < 3; c++)
            xs[p][c] = make_float2(uv[6*p + c], uv[6*p + 3 + c]);

    const float h   = phase ? (float)(10.0/27.0) : (float)(10.0/24.0);
    const int nseg  = phase ? 9 : 1;
    const int nsub  = phase ? 3 : 24;

    #pragma unroll 1
    for (int sg = 0; sg < nseg; sg++) {
        float t = phase ? (float)sg * (float)(10.0/9.0) : 0.0f;

        #pragma unroll 1
        for (int it = 0; it < nsub; it++) {
            float2 k[6][4][3];   // dynamic s-index -> local (cheap vs compute)
            #pragma unroll 1
            for (int s = 0; s < 6; s++) {
                float2 a[4][3];
                #pragma unroll
                for (int p = 0; p < 4; p++)
                    #pragma unroll
                    for (int c = 0; c < 3; c++) a[p][c] = make_float2(0.f, 0.f);
                int base = (s * (s - 1)) >> 1;
                for (int m = 0; m < s; m++) {
                    float ac = cA[base + m];
                    #pragma unroll
                    for (int p = 0; p < 4; p++)
                        #pragma unroll
                        for (int c = 0; c < 3; c++)
                            a[p][c] = f2fma(ac, k[m][p][c], a[p][c]);
                }
                u64 xst[4][3];
                #pragma unroll
                for (int p = 0; p < 4; p++)
                    #pragma unroll
                    for (int c = 0; c < 3; c++) {
                        float2 sv = f2fma(h, a[p][c], xs[p][c]);
                        xst[p][c] = pk2(sv.x, sv.y);
                    }
                float ts = fmaf(cC[s], h, t);
                dyn8(ts, xst, k[s], sw);
            }
            // x += h * (b1 k1 + b3 k3 + b4 k4 + b5 k5 + b6 k6)
            float2 a[4][3];
            #pragma unroll
            for (int p = 0; p < 4; p++)
                #pragma unroll
                for (int c = 0; c < 3; c++) a[p][c] = make_float2(0.f, 0.f);
            for (int m = 0; m < 6; m++) {
                float bc = cB[m];
                #pragma unroll
                for (int p = 0; p < 4; p++)
                    #pragma unroll
                    for (int c = 0; c < 3; c++)
                        a[p][c] = f2fma(bc, k[m][p][c], a[p][c]);
            }
            #pragma unroll
            for (int p = 0; p < 4; p++)
                #pragma unroll
                for (int c = 0; c < 3; c++)
                    xs[p][c] = f2fma(h, a[p][c], xs[p][c]);
            t += h;
        }

        if (phase) {
            float* ot = out + (size_t)3 * B + (size_t)sg * 3 * B + 24 * oid;
            #pragma unroll
            for (int p = 0; p < 4; p++) {
                ot[6*p + 0] = xs[p][0].x; ot[6*p + 1] = xs[p][1].x; ot[6*p + 2] = xs[p][2].x;
                ot[6*p + 3] = xs[p][0].y; ot[6*p + 4] = xs[p][1].y; ot[6*p + 5] = xs[p][2].y;
            }
        }
    }
    if (!phase) {
        float* of = out + 24 * oid;
        #pragma unroll
        for (int p = 0; p < 4; p++) {
            of[6*p + 0] = xs[p][0].x; of[6*p + 1] = xs[p][1].x; of[6*p + 2] = xs[p][2].x;
            of[6*p + 3] = xs[p][0].y; of[6*p + 4] = xs[p][1].y; of[6*p + 5] = xs[p][2].y;
        }
    }
}

extern "C" void kernel_launch(void* const* d_in, const int* in_sizes, int n_in,
                              void* d_out, int out_size) {
    const float* u   = (const float*)d_in[0];
    const float* W1  = (const float*)d_in[1];
    const float* W2  = (const float*)d_in[2];
    const float* W3  = (const float*)d_in[3];
    const float* wb1 = (const float*)d_in[4];
    const float* bb1 = (const float*)d_in[5];
    const float* wb2 = (const float*)d_in[6];
    const float* bb2 = (const float*)d_in[7];
    const float* wb3 = (const float*)d_in[8];
    const float* bb3 = (const float*)d_in[9];
    const float* Wo1 = (const float*)d_in[10];
    const float* Wo2 = (const float*)d_in[11];
    const float* Wo3 = (const float*)d_in[12];
    float* out = (float*)d_out;
    int B = in_sizes[0] / 3;

    int nocts = B >> 3;                     // 16384
    int oblocks = (nocts + 63) / 64;        // 256
    ode_kernel<<<2 * oblocks, 64>>>(u, W1, W2, W3, wb1, bb1, wb2, bb2, wb3, bb3,
                                    Wo1, Wo2, Wo3, out, B);
}

// round 13
// speedup vs baseline: 1.4008x; 1.0004x over previous
#include <cuda_runtime.h>

typedef unsigned long long u64;

// ---------------- DOPRI5 coefficients ----------------
__constant__ float cA[15] = {
    (float)(1.0/5.0),
    (float)(3.0/40.0), (float)(9.0/40.0),
    (float)(44.0/45.0), (float)(-56.0/15.0), (float)(32.0/9.0),
    (float)(19372.0/6561.0), (float)(-25360.0/2187.0), (float)(64448.0/6561.0), (float)(-212.0/729.0),
    (float)(9017.0/3168.0), (float)(-355.0/33.0), (float)(46732.0/5247.0), (float)(49.0/176.0), (float)(-5103.0/18656.0)
};
__constant__ float cB[6] = {
    (float)(35.0/384.0), 0.0f, (float)(500.0/1113.0),
    (float)(125.0/192.0), (float)(-2187.0/6784.0), (float)(11.0/84.0)
};
__constant__ float cC[6] = { 0.0f, (float)(1.0/5.0), (float)(3.0/10.0),
                             (float)(4.0/5.0), (float)(8.0/9.0), 1.0f };

// ---------------- f32x2 helpers ----------------
__device__ __forceinline__ u64 pk2(float lo, float hi) {
    u64 r; asm("mov.b64 %0, {%1, %2};" : "=l"(r) : "f"(lo), "f"(hi)); return r;
}
__device__ __forceinline__ void upk2(u64 v, float& lo, float& hi) {
    asm("mov.b64 {%0, %1}, %2;" : "=f"(lo), "=f"(hi) : "l"(v));
}
__device__ __forceinline__ u64 fma2_(u64 a, u64 b, u64 c) {
    u64 d; asm("fma.rn.f32x2 %0, %1, %2, %3;" : "=l"(d) : "l"(a), "l"(b), "l"(c)); return d;
}
__device__ __forceinline__ float tanhap_(float x) {
    float y; asm("tanh.approx.f32 %0, %1;" : "=f"(y) : "f"(x)); return y;
}
// scalar HW tanh pair (2 MUFU) — the accuracy-proven encoding (rel_err 9e-7 end-to-end)
__device__ __forceinline__ u64 tanh2a_(u64 g) {
    float l, h; upk2(g, l, h);
    return pk2(tanhap_(l), tanhap_(h));
}
__device__ __forceinline__ float2 f2fma(float a, float2 b, float2 c) {
    return make_float2(fmaf(a, b.x, c.x), fmaf(a, b.y, c.y));
}

// ---------------- dynamics for EIGHT particles (four f32x2 pairs) ----------------
// sw[j][0..15] = duplicated-f32x2 weights:
//   0:W1[j,0] 1:W1[j,1] 2:wb1 3:bb1 4:Wo1  5:W2[j,0] 6:W2[j,1] 7:wb2 8:bb2 9:Wo2
//   10:W3[j,0] 11:W3[j,1] 12:W3[j,2] 13:wb3 14:bb3 15:Wo3
// Weights loaded ONCE per j for all 4 pairs; biases computed once per j.
__device__ __forceinline__ void dyn8(float t, const u64 x[4][3], float2 k[4][3],
                                     const u64 (*sw)[16]) {
    u64 tt = pk2(t, t);
    u64 acc[4][3];
    #pragma unroll
    for (int p = 0; p < 4; p++)
        #pragma unroll
        for (int n = 0; n < 3; n++) acc[p][n] = 0ULL;

    #pragma unroll 2
    for (int j = 0; j < 64; j++) {
        const ulonglong2* pw = reinterpret_cast<const ulonglong2*>(sw[j]);
        ulonglong2 q0 = pw[0], q1 = pw[1], q2 = pw[2], q3 = pw[3];
        ulonglong2 q4 = pw[4], q5 = pw[5], q6 = pw[6], q7 = pw[7];

        u64 b1 = fma2_(q1.x, tt, q1.y);   // wb1*t + bb1
        u64 b2 = fma2_(q3.y, tt, q4.x);   // wb2*t + bb2
        u64 b3 = fma2_(q6.y, tt, q7.x);   // wb3*t + bb3

        #pragma unroll
        for (int p = 0; p < 4; p++) {
            u64 g1 = fma2_(q0.x, x[p][0], b1);
            g1 = fma2_(q0.y, x[p][1], g1);
            acc[p][0] = fma2_(q2.x, tanh2a_(g1), acc[p][0]);

            u64 g2 = fma2_(q2.y, x[p][0], b2);
            g2 = fma2_(q3.x, x[p][1], g2);
            acc[p][1] = fma2_(q4.y, tanh2a_(g2), acc[p][1]);

            u64 g3 = fma2_(q5.x, x[p][0], b3);
            g3 = fma2_(q5.y, x[p][1], g3);
            g3 = fma2_(q6.x, x[p][2], g3);
            acc[p][2] = fma2_(q7.y, tanh2a_(g3), acc[p][2]);
        }
    }
    #pragma unroll
    for (int p = 0; p < 4; p++)
        #pragma unroll
        for (int n = 0; n < 3; n++) {
            float lo, hi; upk2(acc[p][n], lo, hi);
            k[p][n] = make_float2(lo, hi);
        }
}

// ---------------- main kernel: 8 particles/thread, 32-thread blocks for SM balance ----------------
// 1024 blocks on 148 SMs -> blocks/SM in {6,7}: scheduling imbalance 1.2% (vs 16% at 512 blocks).
extern "C" __global__ void __launch_bounds__(32, 8)
ode_kernel(const float* __restrict__ u,
           const float* __restrict__ W1, const float* __restrict__ W2, const float* __restrict__ W3,
           const float* __restrict__ wb1, const float* __restrict__ bb1,
           const float* __restrict__ wb2, const float* __restrict__ bb2,
           const float* __restrict__ wb3, const float* __restrict__ bb3,
           const float* __restrict__ Wo1, const float* __restrict__ Wo2, const float* __restrict__ Wo3,
           float* __restrict__ out, int B)
{
    __shared__ __align__(16) u64 sw[64][16];
    int tid = threadIdx.x;
    for (int idx = tid; idx < 64 * 16; idx += blockDim.x) {
        int j = idx >> 4, f = idx & 15;
        float v;
        switch (f) {
            case 0:  v = W1[2*j];    break;
            case 1:  v = W1[2*j+1];  break;
            case 2:  v = wb1[j];     break;
            case 3:  v = bb1[j];     break;
            case 4:  v = Wo1[j];     break;
            case 5:  v = W2[2*j];    break;
            case 6:  v = W2[2*j+1];  break;
            case 7:  v = wb2[j];     break;
            case 8:  v = bb2[j];     break;
            case 9:  v = Wo2[j];     break;
            case 10: v = W3[3*j];    break;
            case 11: v = W3[3*j+1];  break;
            case 12: v = W3[3*j+2];  break;
            case 13: v = wb3[j];     break;
            case 14: v = bb3[j];     break;
            default: v = Wo3[j];     break;
        }
        sw[j][f] = pk2(v, v);
    }
    __syncthreads();

    const int nocts = B >> 3;
    // even blocks: phase 0 (features); odd blocks: phase 1 (trajectory)
    int phase = blockIdx.x & 1;
    int oid = (blockIdx.x >> 1) * blockDim.x + tid;
    if (oid >= nocts) return;

    const float* up = u + 24 * oid;
    float uv[24];
    #pragma unroll
    for (int i = 0; i < 24; i++) uv[i] = up[i];

    // pair p holds particles (8o + 2p, 8o + 2p + 1) in (lo, hi) lanes
    float2 xs[4][3];
    #pragma unroll
    for (int p = 0; p < 4; p++)
        #pragma unroll
        for (int c = 0; c < 3; c++)
            xs[p][c] = make_float2(uv[6*p + c], uv[6*p + 3 + c]);

    const float h   = phase ? (float)(10.0/27.0) : (float)(10.0/24.0);
    const int nseg  = phase ? 9 : 1;
    const int nsub  = phase ? 3 : 24;

    #pragma unroll 1
    for (int sg = 0; sg < nseg; sg++) {
        float t = phase ? (float)sg * (float)(10.0/9.0) : 0.0f;

        #pragma unroll 1
        for (int it = 0; it < nsub; it++) {
            float2 k[6][4][3];   // dynamic s-index -> local (cheap vs compute)
            #pragma unroll 1
            for (int s = 0; s < 6; s++) {
                float2 a[4][3];
                #pragma unroll
                for (int p = 0; p < 4; p++)
                    #pragma unroll
                    for (int c = 0; c < 3; c++) a[p][c] = make_float2(0.f, 0.f);
                int base = (s * (s - 1)) >> 1;
                for (int m = 0; m < s; m++) {
                    float ac = cA[base + m];
                    #pragma unroll
                    for (int p = 0; p < 4; p++)
                        #pragma unroll
                        for (int c = 0; c < 3; c++)
                            a[p][c] = f2fma(ac, k[m][p][c], a[p][c]);
                }
                u64 xst[4][3];
                #pragma unroll
                for (int p = 0; p < 4; p++)
                    #pragma unroll
                    for (int c = 0; c < 3; c++) {
                        float2 sv = f2fma(h, a[p][c], xs[p][c]);
                        xst[p][c] = pk2(sv.x, sv.y);
                    }
                float ts = fmaf(cC[s], h, t);
                dyn8(ts, xst, k[s], sw);
            }
            // x += h * (b1 k1 + b3 k3 + b4 k4 + b5 k5 + b6 k6)
            float2 a[4][3];
            #pragma unroll
            for (int p = 0; p < 4; p++)
                #pragma unroll
                for (int c = 0; c < 3; c++) a[p][c] = make_float2(0.f, 0.f);
            for (int m = 0; m < 6; m++) {
                float bc = cB[m];
                #pragma unroll
                for (int p = 0; p < 4; p++)
                    #pragma unroll
                    for (int c = 0; c < 3; c++)
                        a[p][c] = f2fma(bc, k[m][p][c], a[p][c]);
            }
            #pragma unroll
            for (int p = 0; p < 4; p++)
                #pragma unroll
                for (int c = 0; c < 3; c++)
                    xs[p][c] = f2fma(h, a[p][c], xs[p][c]);
            t += h;
        }

        if (phase) {
            float* ot = out + (size_t)3 * B + (size_t)sg * 3 * B + 24 * oid;
            #pragma unroll
            for (int p = 0; p < 4; p++) {
                ot[6*p + 0] = xs[p][0].x; ot[6*p + 1] = xs[p][1].x; ot[6*p + 2] = xs[p][2].x;
                ot[6*p + 3] = xs[p][0].y; ot[6*p + 4] = xs[p][1].y; ot[6*p + 5] = xs[p][2].y;
            }
        }
    }
    if (!phase) {
        float* of = out + 24 * oid;
        #pragma unroll
        for (int p = 0; p < 4; p++) {
            of[6*p + 0] = xs[p][0].x; of[6*p + 1] = xs[p][1].x; of[6*p + 2] = xs[p][2].x;
            of[6*p + 3] = xs[p][0].y; of[6*p + 4] = xs[p][1].y; of[6*p + 5] = xs[p][2].y;
        }
    }
}

extern "C" void kernel_launch(void* const* d_in, const int* in_sizes, int n_in,
                              void* d_out, int out_size) {
    const float* u   = (const float*)d_in[0];
    const float* W1  = (const float*)d_in[1];
    const float* W2  = (const float*)d_in[2];
    const float* W3  = (const float*)d_in[3];
    const float* wb1 = (const float*)d_in[4];
    const float* bb1 = (const float*)d_in[5];
    const float* wb2 = (const float*)d_in[6];
    const float* bb2 = (const float*)d_in[7];
    const float* wb3 = (const float*)d_in[8];
    const float* bb3 = (const float*)d_in[9];
    const float* Wo1 = (const float*)d_in[10];
    const float* Wo2 = (const float*)d_in[11];
    const float* Wo3 = (const float*)d_in[12];
    float* out = (float*)d_out;
    int B = in_sizes[0] / 3;

    int nocts = B >> 3;                     // 16384
    int oblocks = (nocts + 31) / 32;        // 512
    ode_kernel<<<2 * oblocks, 32>>>(u, W1, W2, W3, wb1, bb1, wb2, bb2, wb3, bb3,
                                    Wo1, Wo2, Wo3, out, B);
}